// round 1
// baseline (speedup 1.0000x reference)
#include <cuda_runtime.h>
#include <mma.h>
#include <cstdint>

using namespace nvcuda;

#define H 1024
#define BZd 256
#define NKEYS 131072
#define NU 7
#define SMEM_FLOATS 27584
#define SMEM_BYTES (SMEM_FLOATS * 4)

__constant__ int c_ud[NU]   = {256, 256, 128, 128, 128, 64, 64};
__constant__ int c_uoff[NU] = {0, 256, 512, 640, 768, 896, 960};

__device__ float g_qrot[BZd * H];
__device__ float g_qhat[BZd * H];
__device__ unsigned long long g_best[NU * BZd];
__device__ float g_cos[NU * BZd];

// ------------------------------------------------------------------
// K1a: qrot = query @ R   (fp32 FFMA, exact)
// grid 32, block 256; each CTA does 8 rows of qrot
// ------------------------------------------------------------------
__global__ void qrot_kernel(const float* __restrict__ q, const float* __restrict__ R) {
    __shared__ float sq[8 * H];
    const int b0 = blockIdx.x * 8;
    const int t = threadIdx.x;
    for (int i = t; i < 8 * H; i += 256) sq[i] = q[(size_t)b0 * H + i];
    __syncthreads();
    float acc[8][4] = {};
    for (int i = 0; i < H; ++i) {
        const float* Rr = R + (size_t)i * H;
        float r0 = Rr[t];
        float r1 = Rr[t + 256];
        float r2 = Rr[t + 512];
        float r3 = Rr[t + 768];
#pragma unroll
        for (int bb = 0; bb < 8; ++bb) {
            float qv = sq[bb * H + i];
            acc[bb][0] += qv * r0;
            acc[bb][1] += qv * r1;
            acc[bb][2] += qv * r2;
            acc[bb][3] += qv * r3;
        }
    }
#pragma unroll
    for (int bb = 0; bb < 8; ++bb)
#pragma unroll
        for (int jj = 0; jj < 4; ++jj)
            g_qrot[(size_t)(b0 + bb) * H + t + jj * 256] = acc[bb][jj];
}

// ------------------------------------------------------------------
// K1b: per-unit normalize qrot -> g_qhat; init g_best
// grid 256 (one per b), block 256
// ------------------------------------------------------------------
__global__ void qhat_kernel() {
    __shared__ float sx[H];
    __shared__ float sred[256];
    const int b = blockIdx.x, t = threadIdx.x;
    for (int i = t; i < H; i += 256) sx[i] = g_qrot[(size_t)b * H + i];
    if (b == 0) {
        // packed(-2.0f, idx=0): ordered bits of -2.0f = ~0xC0000000 = 0x3FFFFFFF
        for (int k = t; k < NU * BZd; k += 256) g_best[k] = 0x3FFFFFFF00000000ULL;
    }
    __syncthreads();
    for (int u = 0; u < NU; ++u) {
        const int d = c_ud[u], off = c_uoff[u];
        float s = 0.0f;
        for (int c = t; c < d; c += 256) { float v = sx[off + c]; s += v * v; }
        sred[t] = s;
        __syncthreads();
        for (int w = 128; w > 0; w >>= 1) {
            if (t < w) sred[t] += sred[t + w];
            __syncthreads();
        }
        float inv = 1.0f / fmaxf(sqrtf(sred[0]), 1e-8f);
        __syncthreads();  // everyone has read sred[0]
        for (int c = t; c < d; c += 256) g_qhat[(size_t)b * H + off + c] = sx[off + c] * inv;
    }
}

// ------------------------------------------------------------------
// K2: main scan kernel (tf32 wmma)
// grid 2048 (64 keys each), block 256 (8 warps)
// ------------------------------------------------------------------
typedef wmma::fragment<wmma::matrix_a, 16, 16, 8, wmma::precision::tf32, wmma::row_major> FragA;
typedef wmma::fragment<wmma::matrix_b, 16, 16, 8, wmma::precision::tf32, wmma::row_major> FragBr;
typedef wmma::fragment<wmma::matrix_b, 16, 16, 8, wmma::precision::tf32, wmma::col_major> FragBc;
typedef wmma::fragment<wmma::accumulator, 16, 16, 8, float> FragC;

// sim accumulation: sims[b(256) x l(64)] += Qhat[b, qoff_g:+Kp] * Krot[l, colbase:+Kp]^T
__device__ __forceinline__ void gemm2_accum(FragC (&cS)[4][2], float* sQ, const float* sKrot,
                                            int qoff_g, int colbase, int Kp,
                                            int t, int wm2, int wn2) {
    for (int ck = 0; ck < Kp; ck += 32) {
        __syncthreads();
#pragma unroll
        for (int r = 0; r < 8; ++r) {
            int id = t + r * 256;
            int row = id >> 3, c4 = (id & 7) * 4;
            *(float4*)(sQ + row * 40 + c4) =
                *(const float4*)(g_qhat + (size_t)row * H + qoff_g + ck + c4);
        }
        __syncthreads();
#pragma unroll
        for (int k8 = 0; k8 < 4; ++k8) {
            FragA a[4];
            FragBc bf[2];
#pragma unroll
            for (int i = 0; i < 4; ++i) {
                wmma::load_matrix_sync(a[i], sQ + (size_t)(wm2 * 64 + 16 * i) * 40 + k8 * 8, 40);
                for (int e = 0; e < a[i].num_elements; ++e)
                    a[i].x[e] = wmma::__float_to_tf32(a[i].x[e]);
            }
#pragma unroll
            for (int j = 0; j < 2; ++j) {
                wmma::load_matrix_sync(bf[j],
                    sKrot + (size_t)(wn2 * 32 + 16 * j) * 136 + colbase + ck + k8 * 8, 136);
                for (int e = 0; e < bf[j].num_elements; ++e)
                    bf[j].x[e] = wmma::__float_to_tf32(bf[j].x[e]);
            }
#pragma unroll
            for (int i = 0; i < 4; ++i)
#pragma unroll
                for (int j = 0; j < 2; ++j)
                    wmma::mma_sync(cS[i][j], a[i], bf[j], cS[i][j]);
        }
    }
}

__device__ __forceinline__ void finalize_unit(FragC (&cS)[4][2], float* sSim,
                                              const float* sNorm2, float* sRN,
                                              int u, int slot, int L0,
                                              int t, int wm2, int wn2) {
    __syncthreads();  // all warps done with GEMM2 (sQ aliases sSim)
#pragma unroll
    for (int i = 0; i < 4; ++i)
#pragma unroll
        for (int j = 0; j < 2; ++j) {
            wmma::store_matrix_sync(sSim + (size_t)(wm2 * 64 + 16 * i) * 72 + wn2 * 32 + 16 * j,
                                    cS[i][j], 72, wmma::mem_row_major);
            wmma::fill_fragment(cS[i][j], 0.0f);
        }
    __syncthreads();
    if (t < 64) sRN[t] = 1.0f / fmaxf(sqrtf(sNorm2[slot * 64 + t]), 1e-3f);
    __syncthreads();
    {
        float best = -1e30f;
        int bi = 0;
        const float* srow = sSim + (size_t)t * 72;
#pragma unroll 8
        for (int l = 0; l < 64; ++l) {
            float v = srow[l] * sRN[l];
            if (v > best) { best = v; bi = l; }  // strict > => first index on ties
        }
        unsigned vb = __float_as_uint(best);
        vb = (vb & 0x80000000u) ? ~vb : (vb | 0x80000000u);
        unsigned long long pk = ((unsigned long long)vb << 32) |
                                (unsigned long long)(0xFFFFFFFFu - (unsigned)(L0 + bi));
        atomicMax(&g_best[u * BZd + t], pk);
    }
}

__global__ void __launch_bounds__(256, 1)
scan_kernel(const float* __restrict__ keys, const float* __restrict__ R) {
    extern __shared__ float sm[];
    float* sKrot  = sm;                       // 64 x 136 = 8704
    float* sX     = sm + 8704;                // aliased region, 18432 floats
    float* sA     = sX;                       // 64 x 40
    float* sB     = sX + 2560;                // 32 x 136
    float* sQ     = sX + 6912;                // 256 x 40
    float* sSim   = sX;                       // 256 x 72 (alias)
    float* sPart  = sm + 8704 + 18432;        // 256
    float* sNorm2 = sPart + 256;              // 128 (2 slots x 64)
    float* sRN    = sNorm2 + 128;             // 64

    const int t = threadIdx.x;
    const int warpId = t >> 5;
    const int L0 = blockIdx.x * 64;
    const int wm = warpId & 1, wn = warpId >> 1;    // GEMM1: 2(M) x 4(N)
    const int wm2 = warpId & 3, wn2 = warpId >> 2;  // GEMM2: 4(M) x 2(N)

    FragC cS[4][2];
#pragma unroll
    for (int i = 0; i < 4; ++i)
#pragma unroll
        for (int j = 0; j < 2; ++j) wmma::fill_fragment(cS[i][j], 0.0f);

    for (int p = 0; p < 8; ++p) {
        const int coff = p * 128;
        FragC cK[2][2];
#pragma unroll
        for (int i = 0; i < 2; ++i)
#pragma unroll
            for (int j = 0; j < 2; ++j) wmma::fill_fragment(cK[i][j], 0.0f);

        // ---------- GEMM1: Krot_panel[64,128] = K[64,1024] @ R[:,coff:coff+128]
        for (int kk = 0; kk < H; kk += 32) {
            __syncthreads();
#pragma unroll
            for (int r = 0; r < 2; ++r) {
                int id = t + r * 256;
                int row = id >> 3, c4 = (id & 7) * 4;
                *(float4*)(sA + row * 40 + c4) =
                    *(const float4*)(keys + (size_t)(L0 + row) * H + kk + c4);
            }
#pragma unroll
            for (int r = 0; r < 4; ++r) {
                int id = t + r * 256;
                int row = id >> 5, c4 = (id & 31) * 4;
                *(float4*)(sB + row * 136 + c4) =
                    *(const float4*)(R + (size_t)(kk + row) * H + coff + c4);
            }
            __syncthreads();
#pragma unroll
            for (int k8 = 0; k8 < 4; ++k8) {
                FragA a[2];
                FragBr bf[2];
#pragma unroll
                for (int i = 0; i < 2; ++i) {
                    wmma::load_matrix_sync(a[i], sA + (size_t)(wm * 32 + 16 * i) * 40 + k8 * 8, 40);
                    for (int e = 0; e < a[i].num_elements; ++e)
                        a[i].x[e] = wmma::__float_to_tf32(a[i].x[e]);
                }
#pragma unroll
                for (int j = 0; j < 2; ++j) {
                    wmma::load_matrix_sync(bf[j], sB + (size_t)(k8 * 8) * 136 + wn * 32 + 16 * j, 136);
                    for (int e = 0; e < bf[j].num_elements; ++e)
                        bf[j].x[e] = wmma::__float_to_tf32(bf[j].x[e]);
                }
#pragma unroll
                for (int i = 0; i < 2; ++i)
#pragma unroll
                    for (int j = 0; j < 2; ++j)
                        wmma::mma_sync(cK[i][j], a[i], bf[j], cK[i][j]);
            }
        }
        __syncthreads();
#pragma unroll
        for (int i = 0; i < 2; ++i)
#pragma unroll
            for (int j = 0; j < 2; ++j)
                wmma::store_matrix_sync(sKrot + (size_t)(wm * 32 + 16 * i) * 136 + wn * 32 + 16 * j,
                                        cK[i][j], 136, wmma::mem_row_major);
        __syncthreads();

        // ---------- norms (fp32 from Krot panel)
        {
            int l = t & 63, q = t >> 6;
            const float* row = sKrot + (size_t)l * 136 + q * 32;
            float s = 0.0f;
#pragma unroll
            for (int i = 0; i < 32; ++i) s += row[i] * row[i];
            sPart[t] = s;
        }
        __syncthreads();
        if (t < 64) {
            if (p < 7) {
                float s = sPart[t] + sPart[t + 64] + sPart[t + 128] + sPart[t + 192];
                bool first = (p == 0) | (p == 2) | (p == 4) | (p == 5) | (p == 6);
                sNorm2[t] = first ? s : (sNorm2[t] + s);
            } else {
                sNorm2[t] = sPart[t] + sPart[t + 64];
                sNorm2[t + 64] = sPart[t + 128] + sPart[t + 192];
            }
        }

        // ---------- GEMM2 + finalize
        if (p < 7) {
            const int u = (p < 2) ? 0 : (p < 4) ? 1 : (p - 2);
            gemm2_accum(cS, sQ, sKrot, coff, 0, 128, t, wm2, wn2);
            bool last = (p == 1) | (p == 3) | (p >= 4);
            if (last) finalize_unit(cS, sSim, sNorm2, sRN, u, 0, L0, t, wm2, wn2);
        } else {
#pragma unroll
            for (int h = 0; h < 2; ++h) {
                gemm2_accum(cS, sQ, sKrot, 896 + h * 64, h * 64, 64, t, wm2, wn2);
                finalize_unit(cS, sSim, sNorm2, sRN, 5 + h, h, L0, t, wm2, wn2);
            }
        }
    }
}

// ------------------------------------------------------------------
// K3: gather winners, exact fp32 diag + cosine
// grid 1792 (u = blk/256, b = blk%256), block 256
// ------------------------------------------------------------------
__global__ void final_kernel(const float* __restrict__ keys, const float* __restrict__ R) {
    __shared__ float sv[H];
    __shared__ float sred[256];
    const int u = blockIdx.x >> 8;
    const int b = blockIdx.x & 255;
    const int t = threadIdx.x;
    unsigned long long pk = g_best[u * BZd + b];
    unsigned idx = 0xFFFFFFFFu - (unsigned)(pk & 0xFFFFFFFFull);
    const float* v = keys + (size_t)idx * H;
    for (int i = t; i < H; i += 256) sv[i] = v[i];
    __syncthreads();
    const int d = c_ud[u], off = c_uoff[u];
    float dg = 0.0f, qc = 0.0f;
    if (t < d) {
        const float* Rc = R + off + t;
#pragma unroll 4
        for (int i = 0; i < H; ++i) dg += sv[i] * Rc[(size_t)i * H];
        qc = g_qrot[(size_t)b * H + off + t];
    }
    float num = qc * dg, nd = dg * dg, nq = qc * qc;
    float tot[3];
    float vals[3] = {num, nd, nq};
#pragma unroll
    for (int r = 0; r < 3; ++r) {
        sred[t] = vals[r];
        __syncthreads();
        for (int w = 128; w > 0; w >>= 1) {
            if (t < w) sred[t] += sred[t + w];
            __syncthreads();
        }
        tot[r] = sred[0];
        __syncthreads();
    }
    if (t == 0) {
        float cosv = tot[0] / (fmaxf(sqrtf(tot[2]), 1e-8f) * fmaxf(sqrtf(tot[1]), 1e-8f));
        g_cos[u * BZd + b] = cosv * (float)d;
    }
}

// ------------------------------------------------------------------
// K4: deterministic ordered reduction to scalar
// ------------------------------------------------------------------
__global__ void reduce_kernel(float* __restrict__ out) {
    __shared__ float sred[256];
    const int t = threadIdx.x;
    float s = 0.0f;
    for (int k = t; k < NU * BZd; k += 256) s += g_cos[k];
    sred[t] = s;
    __syncthreads();
    for (int w = 128; w > 0; w >>= 1) {
        if (t < w) sred[t] += sred[t + w];
        __syncthreads();
    }
    if (t == 0) out[0] = -sred[0] / (float)(BZd * H) * (float)BZd / (float)BZd; // = -sum/(256*1024)
}

// ------------------------------------------------------------------
extern "C" void kernel_launch(void* const* d_in, const int* in_sizes, int n_in,
                              void* d_out, int out_size) {
    const float* query = nullptr;
    const float* keys = nullptr;
    const float* R = nullptr;
    for (int i = 0; i < n_in; ++i) {
        if (in_sizes[i] == BZd * H) query = (const float*)d_in[i];
        else if (in_sizes[i] == NKEYS * H) keys = (const float*)d_in[i];
        else if (in_sizes[i] == H * H) R = (const float*)d_in[i];
    }
    if (!query) query = (const float*)d_in[0];
    if (!keys) keys = (const float*)d_in[1];
    if (!R) R = (const float*)d_in[2];
    float* out = (float*)d_out;

    cudaFuncSetAttribute(scan_kernel, cudaFuncAttributeMaxDynamicSharedMemorySize, SMEM_BYTES);

    qrot_kernel<<<32, 256>>>(query, R);
    qhat_kernel<<<256, 256>>>();
    scan_kernel<<<NKEYS / 64, 256, SMEM_BYTES>>>(keys, R);
    final_kernel<<<NU * BZd, 256>>>(keys, R);
    reduce_kernel<<<1, 256>>>(out);
}